// round 15
// baseline (speedup 1.0000x reference)
#include <cuda_runtime.h>

// Torch_SINDy streaming kernel — FINAL champion (re-bench).
// 160MiB single-pass stream (16B in / 4B out per row).
// Search record R3-R14: one-shot grid + 128-thread blocks + block-strided
// MLP=8 front-batched LDG.128.cs + __stcs stores is optimal
// (24.0us kernel / 76.5% DRAM best draw; 24.0-25.3us noise band).
// All structural alternatives regressed: persistent loop (R4), work-steal
// double-buffer (R6), MLP=16 (R8), cp.async staging (R9), LDG.256 (R11),
// TMA bulk staging (R12), packed stores (R5) -> 70-73% DRAM.
// The ~6TB/s plateau is the HBM read/write-turnaround roofline for this
// 4:1 traffic mix. Data loads issue first; coefficient broadcast loads and
// products complete under their DRAM-latency shadow.

#define ITEMS 8
#define THREADS 128
#define CHUNK (THREADS * ITEMS)   // 1024 rows per block

__device__ __forceinline__ float sindy_row(float4 v, const float* c) {
    float u  = v.x;
    float u2 = u * u;
    float u3 = u2 * u;
    float y = v.y, z = v.z, w = v.w;
    float r = u * c[0] + u2 * c[1] + u3 * c[2]
            + y * c[3] + z * c[4] + w * c[5];
    r += y * (u * c[6]  + u2 * c[7]  + u3 * c[8]);
    r += z * (u * c[9]  + u2 * c[10] + u3 * c[11]);
    r += w * (u * c[12] + u2 * c[13] + u3 * c[14]);
    return r;
}

__device__ __forceinline__ void load_coeffs(const float* __restrict__ coeff,
                                            const float* __restrict__ base,
                                            float* c) {
    const float4* c4 = (const float4*)coeff;
    const float4* b4 = (const float4*)base;
#pragma unroll
    for (int q = 0; q < 3; ++q) {
        float4 cv = __ldg(&c4[q]);
        float4 bv = __ldg(&b4[q]);
        c[q*4+0] = cv.x * bv.x;
        c[q*4+1] = cv.y * bv.y;
        c[q*4+2] = cv.z * bv.z;
        c[q*4+3] = cv.w * bv.w;
    }
#pragma unroll
    for (int q = 12; q < 15; ++q)
        c[q] = __ldg(&coeff[q]) * __ldg(&base[q]);
}

// Exact path: grid covers n exactly, no guards. 8 front-batched coalesced
// LDG.128.cs first; coefficient loads complete under their DRAM shadow.
__global__ void __launch_bounds__(THREADS)
sindy_kernel_exact(const float4* __restrict__ big_u,
                   const float*  __restrict__ coeff,
                   const float*  __restrict__ base,
                   float*        __restrict__ out) {
    int base_i = blockIdx.x * CHUNK + threadIdx.x;

    float4 v[ITEMS];
#pragma unroll
    for (int k = 0; k < ITEMS; ++k)
        v[k] = __ldcs(&big_u[base_i + k * THREADS]);

    float c[15];
    load_coeffs(coeff, base, c);

#pragma unroll
    for (int k = 0; k < ITEMS; ++k)
        __stcs(&out[base_i + k * THREADS], sindy_row(v[k], c));
}

// Guarded tail for arbitrary n.
__global__ void __launch_bounds__(THREADS)
sindy_tail(const float4* __restrict__ big_u,
           const float*  __restrict__ coeff,
           const float*  __restrict__ base,
           float*        __restrict__ out,
           int start, int n) {
    float c[15];
    load_coeffs(coeff, base, c);
    int i = start + blockIdx.x * THREADS + threadIdx.x;
    if (i < n) {
        float4 v = __ldcs(&big_u[i]);
        __stcs(&out[i], sindy_row(v, c));
    }
}

extern "C" void kernel_launch(void* const* d_in, const int* in_sizes, int n_in,
                              void* d_out, int out_size) {
    const float4* big_u = (const float4*)d_in[0];   // [N,4] f32
    const float*  coeff = (const float*)d_in[1];    // [15]  f32
    const float*  base  = (const float*)d_in[2];    // [15]  f32
    float* out = (float*)d_out;                     // [N,1] f32

    int n = in_sizes[0] / 4;   // rows
    int n_full = n / CHUNK;

    if (n_full > 0)
        sindy_kernel_exact<<<n_full, THREADS>>>(big_u, coeff, base, out);

    int tail_start = n_full * CHUNK;
    int tail = n - tail_start;
    if (tail > 0) {
        int tblocks = (tail + THREADS - 1) / THREADS;
        sindy_tail<<<tblocks, THREADS>>>(big_u, coeff, base, out, tail_start, n);
    }
}

// round 16
// speedup vs baseline: 1.0736x; 1.0736x over previous
#include <cuda_runtime.h>

// Torch_SINDy streaming kernel — champion + write-through stores probe.
// Champion (R7/R10/R14): one-shot, 128-thr blocks, block-strided MLP=8
// front-batched LDG.128.cs. Identical-binary noise band 24.0-26.6us kernel
// (DVFS, clock-control none). Last untested lever: st.global.wt on the
// write-once output — avoids L2 dirty-line writeback bursts interleaving
// with the read stream at the HBM controller (the suspected source of the
// ~76% read/write-turnaround plateau).

#define ITEMS 8
#define THREADS 128
#define CHUNK (THREADS * ITEMS)   // 1024 rows per block

__device__ __forceinline__ float sindy_row(float4 v, const float* c) {
    float u  = v.x;
    float u2 = u * u;
    float u3 = u2 * u;
    float y = v.y, z = v.z, w = v.w;
    float r = u * c[0] + u2 * c[1] + u3 * c[2]
            + y * c[3] + z * c[4] + w * c[5];
    r += y * (u * c[6]  + u2 * c[7]  + u3 * c[8]);
    r += z * (u * c[9]  + u2 * c[10] + u3 * c[11]);
    r += w * (u * c[12] + u2 * c[13] + u3 * c[14]);
    return r;
}

__device__ __forceinline__ void load_coeffs(const float* __restrict__ coeff,
                                            const float* __restrict__ base,
                                            float* c) {
    const float4* c4 = (const float4*)coeff;
    const float4* b4 = (const float4*)base;
#pragma unroll
    for (int q = 0; q < 3; ++q) {
        float4 cv = __ldg(&c4[q]);
        float4 bv = __ldg(&b4[q]);
        c[q*4+0] = cv.x * bv.x;
        c[q*4+1] = cv.y * bv.y;
        c[q*4+2] = cv.z * bv.z;
        c[q*4+3] = cv.w * bv.w;
    }
#pragma unroll
    for (int q = 12; q < 15; ++q)
        c[q] = __ldg(&coeff[q]) * __ldg(&base[q]);
}

// Exact path: grid covers n exactly, no guards. 8 front-batched coalesced
// LDG.128.cs first; coefficient loads complete under their DRAM shadow.
// Output via write-through stores (no L2 dirty-writeback).
__global__ void __launch_bounds__(THREADS)
sindy_kernel_exact(const float4* __restrict__ big_u,
                   const float*  __restrict__ coeff,
                   const float*  __restrict__ base,
                   float*        __restrict__ out) {
    int base_i = blockIdx.x * CHUNK + threadIdx.x;

    float4 v[ITEMS];
#pragma unroll
    for (int k = 0; k < ITEMS; ++k)
        v[k] = __ldcs(&big_u[base_i + k * THREADS]);

    float c[15];
    load_coeffs(coeff, base, c);

#pragma unroll
    for (int k = 0; k < ITEMS; ++k)
        __stwt(&out[base_i + k * THREADS], sindy_row(v[k], c));
}

// Guarded tail for arbitrary n.
__global__ void __launch_bounds__(THREADS)
sindy_tail(const float4* __restrict__ big_u,
           const float*  __restrict__ coeff,
           const float*  __restrict__ base,
           float*        __restrict__ out,
           int start, int n) {
    float c[15];
    load_coeffs(coeff, base, c);
    int i = start + blockIdx.x * THREADS + threadIdx.x;
    if (i < n) {
        float4 v = __ldcs(&big_u[i]);
        __stwt(&out[i], sindy_row(v, c));
    }
}

extern "C" void kernel_launch(void* const* d_in, const int* in_sizes, int n_in,
                              void* d_out, int out_size) {
    const float4* big_u = (const float4*)d_in[0];   // [N,4] f32
    const float*  coeff = (const float*)d_in[1];    // [15]  f32
    const float*  base  = (const float*)d_in[2];    // [15]  f32
    float* out = (float*)d_out;                     // [N,1] f32

    int n = in_sizes[0] / 4;   // rows
    int n_full = n / CHUNK;

    if (n_full > 0)
        sindy_kernel_exact<<<n_full, THREADS>>>(big_u, coeff, base, out);

    int tail_start = n_full * CHUNK;
    int tail = n - tail_start;
    if (tail > 0) {
        int tblocks = (tail + THREADS - 1) / THREADS;
        sindy_tail<<<tblocks, THREADS>>>(big_u, coeff, base, out, tail_start, n);
    }
}

// round 17
// speedup vs baseline: 1.1516x; 1.0727x over previous
#include <cuda_runtime.h>

// Torch_SINDy streaming kernel — FINAL: champion + L2::256B read hint.
// Champion shape (R7/R10/R14/R16): one-shot grid, 128-thread blocks,
// block-strided MLP=8 front-batched 16B loads, coefficient loads under the
// data loads' DRAM shadow, write-through stores (R16: neutral, kept).
// Identical-binary noise band: 24.0-26.6us kernel, 69-77% DRAM (DVFS).
// All structural alternatives (persistent, work-steal, MLP=16, packed
// stores, LDG.256, cp.async, TMA) measured strictly worse.
// Final micro-probe: ld.global.nc.L2::256B on the read stream — wider L2
// fill granularity per request, fewer DRAM row activations per byte.

#define ITEMS 8
#define THREADS 128
#define CHUNK (THREADS * ITEMS)   // 1024 rows per block

__device__ __forceinline__ float4 ldg_cs_256B(const float4* p) {
    float4 r;
    asm volatile("ld.global.nc.L1::no_allocate.L2::256B.v4.f32 "
                 "{%0,%1,%2,%3}, [%4];"
                 : "=f"(r.x), "=f"(r.y), "=f"(r.z), "=f"(r.w)
                 : "l"(p));
    return r;
}

__device__ __forceinline__ float sindy_row(float4 v, const float* c) {
    float u  = v.x;
    float u2 = u * u;
    float u3 = u2 * u;
    float y = v.y, z = v.z, w = v.w;
    float r = u * c[0] + u2 * c[1] + u3 * c[2]
            + y * c[3] + z * c[4] + w * c[5];
    r += y * (u * c[6]  + u2 * c[7]  + u3 * c[8]);
    r += z * (u * c[9]  + u2 * c[10] + u3 * c[11]);
    r += w * (u * c[12] + u2 * c[13] + u3 * c[14]);
    return r;
}

__device__ __forceinline__ void load_coeffs(const float* __restrict__ coeff,
                                            const float* __restrict__ base,
                                            float* c) {
    const float4* c4 = (const float4*)coeff;
    const float4* b4 = (const float4*)base;
#pragma unroll
    for (int q = 0; q < 3; ++q) {
        float4 cv = __ldg(&c4[q]);
        float4 bv = __ldg(&b4[q]);
        c[q*4+0] = cv.x * bv.x;
        c[q*4+1] = cv.y * bv.y;
        c[q*4+2] = cv.z * bv.z;
        c[q*4+3] = cv.w * bv.w;
    }
#pragma unroll
    for (int q = 12; q < 15; ++q)
        c[q] = __ldg(&coeff[q]) * __ldg(&base[q]);
}

// Exact path: grid covers n exactly, no guards. 8 front-batched coalesced
// loads first (L2::256B fill hint); coefficient loads complete under their
// DRAM shadow; write-through stores.
__global__ void __launch_bounds__(THREADS)
sindy_kernel_exact(const float4* __restrict__ big_u,
                   const float*  __restrict__ coeff,
                   const float*  __restrict__ base,
                   float*        __restrict__ out) {
    int base_i = blockIdx.x * CHUNK + threadIdx.x;

    float4 v[ITEMS];
#pragma unroll
    for (int k = 0; k < ITEMS; ++k)
        v[k] = ldg_cs_256B(&big_u[base_i + k * THREADS]);

    float c[15];
    load_coeffs(coeff, base, c);

#pragma unroll
    for (int k = 0; k < ITEMS; ++k)
        __stwt(&out[base_i + k * THREADS], sindy_row(v[k], c));
}

// Guarded tail for arbitrary n.
__global__ void __launch_bounds__(THREADS)
sindy_tail(const float4* __restrict__ big_u,
           const float*  __restrict__ coeff,
           const float*  __restrict__ base,
           float*        __restrict__ out,
           int start, int n) {
    float c[15];
    load_coeffs(coeff, base, c);
    int i = start + blockIdx.x * THREADS + threadIdx.x;
    if (i < n) {
        float4 v = __ldcs(&big_u[i]);
        __stwt(&out[i], sindy_row(v, c));
    }
}

extern "C" void kernel_launch(void* const* d_in, const int* in_sizes, int n_in,
                              void* d_out, int out_size) {
    const float4* big_u = (const float4*)d_in[0];   // [N,4] f32
    const float*  coeff = (const float*)d_in[1];    // [15]  f32
    const float*  base  = (const float*)d_in[2];    // [15]  f32
    float* out = (float*)d_out;                     // [N,1] f32

    int n = in_sizes[0] / 4;   // rows
    int n_full = n / CHUNK;

    if (n_full > 0)
        sindy_kernel_exact<<<n_full, THREADS>>>(big_u, coeff, base, out);

    int tail_start = n_full * CHUNK;
    int tail = n - tail_start;
    if (tail > 0) {
        int tblocks = (tail + THREADS - 1) / THREADS;
        sindy_tail<<<tblocks, THREADS>>>(big_u, coeff, base, out, tail_start, n);
    }
}